// round 15
// baseline (speedup 1.0000x reference)
#include <cuda_runtime.h>
#include <cuda_bf16.h>
#include <cstdint>

// Problem constants: outputs [64,512,1000] f32, labels [64,512] i32
#define LBL 1000
#define FAG 32                      // k_fa grid (co-resident: 32 blocks)

__device__ __align__(16) int g_first[1024];     // static zero-init; k_scan re-zeros
__device__ __align__(16) int g_argm_ev[1024];   // argmax of each label's first row
__device__ __align__(16) int g_idx[1024];       // pinv (inverse permutation)
__device__ unsigned g_done;                     // monotonic: ++ per replay by k_scan
__device__ unsigned g_target;                   // snapshot: g_done+1 (by k_fa)
__device__ unsigned g_bar;                      // monotonic barrier counter

static __device__ __forceinline__ uint32_t smem_u32(const void* p) {
    uint32_t a;
    asm("{ .reg .u64 t; cvta.to.shared.u64 t, %1; cvt.u32.u64 %0, t; }"
        : "=r"(a) : "l"(p));
    return a;
}

// ---------------------------------------------------------------------------
// K_FA: fused first-occurrence + event argmax (one launch, one grid barrier).
// Grid 32 x 1024 -- co-resident on 148 SMs, so the spin barrier is safe.
// Phase 1: first occurrence per label, encoded max(N-i) (empty state 0;
//          static zero init, k_scan self-resets). One atomic per thread.
// Barrier: monotonic ticket (replay-safe, no reset kernel).
// Phase 2: warp W argmaxes label W's first-occurrence row (<=1000 rows, 4 MB).
// ---------------------------------------------------------------------------
__global__ __launch_bounds__(1024) void k_fa(const float* __restrict__ in,
                                             const int* __restrict__ labels,
                                             int N) {
    int t    = threadIdx.x;
    int lane = t & 31;
    int w    = t >> 5;
    int bid  = blockIdx.x;

    if (bid == 0 && t == 0)
        g_target = g_done + 1;       // gather-release target (stream-serial)

    // ---- Phase 1: first occurrence ----------------------------------------
    for (int i = bid * 1024 + t; i < N; i += FAG * 1024)
        atomicMax(&g_first[labels[i]], N - i);

    // ---- grid barrier (monotonic ticket) ----------------------------------
    __syncthreads();
    if (t == 0) {
        __threadfence();
        unsigned my  = atomicAdd(&g_bar, 1u);
        unsigned tgt = my - (my % FAG) + FAG;
        while (*(volatile unsigned*)&g_bar < tgt) { }
    }
    __syncthreads();

    // ---- Phase 2: argmax of each label's first-occurrence row -------------
    int W = bid * 32 + w;            // 1024 warps >= LBL
    if (W >= LBL) return;
    int enc = __ldcg(&g_first[W]);
    if (enc <= 0) return;            // label never occurs
    int row = N - enc;               // first-occurrence row

    const float4* rp = reinterpret_cast<const float4*>(in) + (size_t)row * 250;
    float bv = -3.402823466e38f;
    int   bi = 0;
#pragma unroll
    for (int it = 0; it < 7; ++it) {             // k = lane + 32*it <= 223
        int k = lane + it * 32;
        float4 v = rp[k];
        int b = k * 4;
        if (v.x > bv) { bv = v.x; bi = b;     }
        if (v.y > bv) { bv = v.y; bi = b + 1; }
        if (v.z > bv) { bv = v.z; bi = b + 2; }
        if (v.w > bv) { bv = v.w; bi = b + 3; }
    }
    if (lane < 26) {                              // tail: k = lane + 224 < 250
        int k = lane + 224;
        float4 v = rp[k];
        int b = k * 4;
        if (v.x > bv) { bv = v.x; bi = b;     }
        if (v.y > bv) { bv = v.y; bi = b + 1; }
        if (v.z > bv) { bv = v.z; bi = b + 2; }
        if (v.w > bv) { bv = v.w; bi = b + 3; }
    }
#pragma unroll
    for (int off = 16; off > 0; off >>= 1) {
        float ov = __shfl_down_sync(0xFFFFFFFFu, bv, off);
        int   oi = __shfl_down_sync(0xFFFFFFFFu, bi, off);
        if (ov > bv || (ov == bv && oi < bi)) { bv = ov; bi = oi; }
    }
    if (lane == 0) g_argm_ev[W] = bi;
}

// ---------------------------------------------------------------------------
// K2: single block. Triggers programmatic launch of k_gather AT ENTRY so the
// gather's wave-1 row loads overlap this kernel. Releases the gather via
// g_done++ (after threadfence) when g_idx is published.
//   Phase A: rank events by row via 32768-bit bitmap + popc prefix-sum.
//   Phase B: warp-speculative batch scan (warp 0).
// ---------------------------------------------------------------------------
__global__ __launch_bounds__(1024) void k_scan(int N) {
    cudaTriggerProgrammaticLaunchCompletion();   // let k_gather launch NOW

    __shared__ unsigned  sbit[1024];   // 32768-bit row bitmap
    __shared__ int       sexc[1024];   // exclusive popc prefix per word
    __shared__ long long ev[1088];     // packed (m << 32) | lab, sorted by row
    __shared__ int       pinv[1024];
    __shared__ int       stamp[1024];  // per-cell lane stamps for hazard detect
    __shared__ int       wsum[32];
    __shared__ int       sE;

    int t = threadIdx.x;
    int lane = t & 31, w = t >> 5;

    // ---- prework (independent of predecessors) ----------------------------
    sbit[t]  = 0u;
    pinv[t]  = t;
    stamp[t] = 63;
    ev[t]    = ((long long)1023 << 32) | 1023u;     // dummy everywhere
    if (t < 64) ev[1024 + t] = ((long long)1023 << 32) | 1023u;

    cudaGridDependencySynchronize();   // wait k_fa (PDL)

    int enc = (t < LBL) ? g_first[t] : 0;
    g_first[t] = 0;                    // reset for next graph replay
    int myf = (enc > 0) ? (N - enc) : -1;
    __syncthreads();

    if (myf >= 0)
        atomicOr(&sbit[myf >> 5], 1u << (myf & 31));
    __syncthreads();

    // block prefix-sum of per-word popcounts
    unsigned word = sbit[t];
    int c = __popc(word);
    int x = c;
#pragma unroll
    for (int o = 1; o < 32; o <<= 1) {
        int y = __shfl_up_sync(0xFFFFFFFFu, x, o);
        if (lane >= o) x += y;
    }
    if (lane == 31) wsum[w] = x;
    __syncthreads();
    if (t < 32) {
        int v = wsum[t];
        int iv = v;
#pragma unroll
        for (int o = 1; o < 32; o <<= 1) {
            int y = __shfl_up_sync(0xFFFFFFFFu, iv, o);
            if (t >= o) iv += y;
        }
        wsum[t] = iv - v;          // exclusive warp offset
        if (t == 31) sE = iv;      // total number of events
    }
    __syncthreads();
    sexc[t] = wsum[w] + (x - c);
    __syncthreads();

    if (myf >= 0) {
        unsigned wv = sbit[myf >> 5];
        int rank = sexc[myf >> 5] + __popc(wv & ((1u << (myf & 31)) - 1u));
        ev[rank] = ((long long)g_argm_ev[t] << 32) | (unsigned)t;
    }
    __syncthreads();

    // Phase B: warp-speculative batch loop (warp 0 only)
    if (t < 32) {
        const unsigned FULL = 0xFFFFFFFFu;
        int E = sE;
        int base = 0;
        while (base < E) {
            long long ee = ev[base + lane];
            int m   = (int)(ee >> 32);
            int lab = (int)(ee & 0xFFFFFFFFLL);
            atomicMin(&stamp[lab], lane);     // no dependence on r: issue early
            int r   = pinv[m];                // speculative (round-start state)
            int pl  = pinv[lab];
            int pr  = pinv[r];
            atomicMin(&stamp[r], lane);
            __syncwarp(FULL);
            int hz = (stamp[m] < lane) | (stamp[r] < lane) | (stamp[lab] < lane);
            unsigned bal = __ballot_sync(FULL, hz);
            int f = bal ? (__ffs(bal) - 1) : 32;    // f >= 1 always (lane 0 safe)
            stamp[r]   = 63;                   // reset stamps (post-ballot sync)
            stamp[lab] = 63;
            if (lane < f) {                    // commit conflict-free prefix
                pinv[r]   = pl;
                pinv[lab] = pr;
            }
            __syncwarp(FULL);
            base += f;
        }
    }
    __syncthreads();

    if (t < LBL) g_idx[t] = pinv[t];   // publish pinv
    __threadfence();
    __syncthreads();
    if (t == 0) atomicAdd(&g_done, 1u);        // release the gather
}

// ---------------------------------------------------------------------------
// K3: out[n, pinv[k]] = in[n, k]. Launched programmatically while k_scan runs:
// issues ALL row loads (MLP=8, wave-1 ~24 MB overlaps the scan), then spins on
// g_done. sidx read via __ldcg (L2-coherent). Scatter-STS + TMA bulk store.
// ---------------------------------------------------------------------------
__global__ __launch_bounds__(256) void k_gather(const float* __restrict__ in,
                                                float* __restrict__ out, int N) {
    __shared__ int4 sidx[250];                       // pinv, packed
    __shared__ __align__(16) float srow[8][1000];    // 4 KB slab per warp

    int t    = threadIdx.x;
    int wid  = t >> 5;
    int lane = t & 31;

    // ---- prework: all row loads in flight (overlaps k_scan) ---------------
    int row = blockIdx.x * 8 + wid;
    float4 v[8];
    if (row < N) {
        const float4* rp = reinterpret_cast<const float4*>(in + (size_t)row * 1000);
#pragma unroll
        for (int it = 0; it < 8; ++it) {
            int k = lane + it * 32;
            if (k < 250) v[it] = __ldcs(&rp[k]);
        }
    }

    // ---- wait for g_idx (monotonic flag; target snapshotted by k_fa) ------
    if (t == 0) {
        unsigned tgt = __ldcg(&g_target);
        while (__ldcg(&g_done) < tgt) __nanosleep(64);
    }
    __syncthreads();

    if (t < 250) sidx[t] = __ldcg(reinterpret_cast<const int4*>(g_idx) + t);
    __syncthreads();

    if (row < N) {
        float* my = &srow[wid][0];
#pragma unroll
        for (int it = 0; it < 8; ++it) {
            int k = lane + it * 32;
            if (k < 250) {
                int4 p = sidx[k];
                my[p.x] = v[it].x;     // permuted scatter into smem
                my[p.y] = v[it].y;
                my[p.z] = v[it].z;
                my[p.w] = v[it].w;
            }
        }
        // order the generic STS above before the async-proxy smem reads
        asm volatile("fence.proxy.async.shared::cta;" ::: "memory");
        __syncwarp();
        if (lane == 0) {
            uint32_t saddr = smem_u32(my);
            float*   gdst  = out + (size_t)row * 1000;
            asm volatile(
                "cp.async.bulk.global.shared::cta.bulk_group [%0], [%1], %2;"
                :: "l"(gdst), "r"(saddr), "r"(4000) : "memory");
            asm volatile("cp.async.bulk.commit_group;" ::: "memory");
            asm volatile("cp.async.bulk.wait_group 0;" ::: "memory");
        }
        __syncwarp();
    }
}

// ---------------------------------------------------------------------------
// host: PDL launches (programmatic stream serialization on the capture stream)
// ---------------------------------------------------------------------------
template <typename F, typename... Args>
static void launch_pdl(F func, dim3 grid, dim3 block, Args... args) {
    cudaLaunchConfig_t cfg = {};
    cfg.gridDim  = grid;
    cfg.blockDim = block;
    cfg.dynamicSmemBytes = 0;
    cfg.stream = 0;                      // legacy default stream (captured)
    cudaLaunchAttribute attr[1];
    attr[0].id = cudaLaunchAttributeProgrammaticStreamSerialization;
    attr[0].val.programmaticStreamSerializationAllowed = 1;
    cfg.attrs = attr;
    cfg.numAttrs = 1;
    cudaLaunchKernelEx(&cfg, func, args...);
}

extern "C" void kernel_launch(void* const* d_in, const int* in_sizes, int n_in,
                              void* d_out, int out_size) {
    const float* in     = (const float*)d_in[0];
    const int*   labels = (const int*)d_in[1];
    float*       out    = (float*)d_out;
    int N = in_sizes[1];   // 32768 rows; L = 1000

    k_fa<<<FAG, 1024>>>(in, labels, N);
    launch_pdl(k_scan,   dim3(1),           dim3(1024), N);
    launch_pdl(k_gather, dim3((N + 7) / 8), dim3(256), in, out, N);
}

// round 16
// speedup vs baseline: 1.0032x; 1.0032x over previous
#include <cuda_runtime.h>
#include <cuda_bf16.h>
#include <cstdint>

// Problem constants: outputs [64,512,1000] f32, labels [64,512] i32
#define LBL 1000
#define FAG 256                     // k_fa grid (256 blocks x 256 thr, co-resident)

__device__ __align__(16) int g_first[1024];     // static zero-init; k_scan re-zeros
__device__ __align__(16) int g_argm_ev[1024];   // argmax of each label's first row
__device__ __align__(16) int g_idx[1024];       // pinv (inverse permutation)
__device__ unsigned g_done;                     // monotonic: ++ per replay by k_scan
__device__ unsigned g_target;                   // snapshot: g_done+1 (by k_fa)
__device__ unsigned g_bar;                      // monotonic barrier counter

static __device__ __forceinline__ uint32_t smem_u32(const void* p) {
    uint32_t a;
    asm("{ .reg .u64 t; cvta.to.shared.u64 t, %1; cvt.u32.u64 %0, t; }"
        : "=r"(a) : "l"(p));
    return a;
}

// ---------------------------------------------------------------------------
// K_FA: fused first-occurrence + event argmax. 256 blocks x 256 threads:
// full-chip parallelism in BOTH phases (R15's grid=32 starved phase 2).
// Phase 1: one label + one atomicMax per thread (encoded max(N-i); empty=0).
// Barrier: monotonic ticket over 256 co-resident blocks (replay-safe).
// Phase 2: warp W argmaxes label W's first-occurrence row (4 MB, 148 SMs).
// ---------------------------------------------------------------------------
__global__ __launch_bounds__(256) void k_fa(const float* __restrict__ in,
                                            const int* __restrict__ labels,
                                            int N) {
    int t    = threadIdx.x;
    int lane = t & 31;
    int w    = t >> 5;
    int bid  = blockIdx.x;

    if (bid == 0 && t == 0)
        g_target = g_done + 1;       // gather-release target (stream-serial)

    // ---- Phase 1: first occurrence -----------------------------------------
    for (int i = bid * 256 + t; i < N; i += FAG * 256)
        atomicMax(&g_first[labels[i]], N - i);

    // ---- grid barrier (monotonic ticket, 256 arrivals) ---------------------
    __syncthreads();
    if (t == 0) {
        __threadfence();
        unsigned my  = atomicAdd(&g_bar, 1u);
        unsigned tgt = my - (my % FAG) + FAG;
        while (*(volatile unsigned*)&g_bar < tgt) { }
    }
    __syncthreads();

    // ---- Phase 2: argmax of each label's first-occurrence row --------------
    int W = bid * 8 + w;             // 2048 warps >= LBL
    if (W >= LBL) return;
    int enc = __ldcg(&g_first[W]);
    if (enc <= 0) return;            // label never occurs
    int row = N - enc;               // first-occurrence row

    const float4* rp = reinterpret_cast<const float4*>(in) + (size_t)row * 250;
    float bv = -3.402823466e38f;
    int   bi = 0;
#pragma unroll
    for (int it = 0; it < 7; ++it) {             // k = lane + 32*it <= 223
        int k = lane + it * 32;
        float4 v = rp[k];
        int b = k * 4;
        if (v.x > bv) { bv = v.x; bi = b;     }
        if (v.y > bv) { bv = v.y; bi = b + 1; }
        if (v.z > bv) { bv = v.z; bi = b + 2; }
        if (v.w > bv) { bv = v.w; bi = b + 3; }
    }
    if (lane < 26) {                              // tail: k = lane + 224 < 250
        int k = lane + 224;
        float4 v = rp[k];
        int b = k * 4;
        if (v.x > bv) { bv = v.x; bi = b;     }
        if (v.y > bv) { bv = v.y; bi = b + 1; }
        if (v.z > bv) { bv = v.z; bi = b + 2; }
        if (v.w > bv) { bv = v.w; bi = b + 3; }
    }
#pragma unroll
    for (int off = 16; off > 0; off >>= 1) {
        float ov = __shfl_down_sync(0xFFFFFFFFu, bv, off);
        int   oi = __shfl_down_sync(0xFFFFFFFFu, bi, off);
        if (ov > bv || (ov == bv && oi < bi)) { bv = ov; bi = oi; }
    }
    if (lane == 0) g_argm_ev[W] = bi;
}

// ---------------------------------------------------------------------------
// K2: single block. Triggers programmatic launch of k_gather AT ENTRY so the
// gather's wave-1 row loads overlap this kernel. Releases the gather via
// g_done++ (after threadfence) when g_idx is published.
//   Phase A: rank events by row via 32768-bit bitmap + popc prefix-sum.
//   Phase B: warp-speculative batch scan (warp 0).
// ---------------------------------------------------------------------------
__global__ __launch_bounds__(1024) void k_scan(int N) {
    cudaTriggerProgrammaticLaunchCompletion();   // let k_gather launch NOW

    __shared__ unsigned  sbit[1024];   // 32768-bit row bitmap
    __shared__ int       sexc[1024];   // exclusive popc prefix per word
    __shared__ long long ev[1088];     // packed (m << 32) | lab, sorted by row
    __shared__ int       pinv[1024];
    __shared__ int       stamp[1024];  // per-cell lane stamps for hazard detect
    __shared__ int       wsum[32];
    __shared__ int       sE;

    int t = threadIdx.x;
    int lane = t & 31, w = t >> 5;

    // ---- prework (independent of predecessors) ----------------------------
    sbit[t]  = 0u;
    pinv[t]  = t;
    stamp[t] = 63;
    ev[t]    = ((long long)1023 << 32) | 1023u;     // dummy everywhere
    if (t < 64) ev[1024 + t] = ((long long)1023 << 32) | 1023u;

    cudaGridDependencySynchronize();   // wait k_fa (PDL)

    int enc = (t < LBL) ? g_first[t] : 0;
    g_first[t] = 0;                    // reset for next graph replay
    int myf = (enc > 0) ? (N - enc) : -1;
    __syncthreads();

    if (myf >= 0)
        atomicOr(&sbit[myf >> 5], 1u << (myf & 31));
    __syncthreads();

    // block prefix-sum of per-word popcounts
    unsigned word = sbit[t];
    int c = __popc(word);
    int x = c;
#pragma unroll
    for (int o = 1; o < 32; o <<= 1) {
        int y = __shfl_up_sync(0xFFFFFFFFu, x, o);
        if (lane >= o) x += y;
    }
    if (lane == 31) wsum[w] = x;
    __syncthreads();
    if (t < 32) {
        int v = wsum[t];
        int iv = v;
#pragma unroll
        for (int o = 1; o < 32; o <<= 1) {
            int y = __shfl_up_sync(0xFFFFFFFFu, iv, o);
            if (t >= o) iv += y;
        }
        wsum[t] = iv - v;          // exclusive warp offset
        if (t == 31) sE = iv;      // total number of events
    }
    __syncthreads();
    sexc[t] = wsum[w] + (x - c);
    __syncthreads();

    if (myf >= 0) {
        unsigned wv = sbit[myf >> 5];
        int rank = sexc[myf >> 5] + __popc(wv & ((1u << (myf & 31)) - 1u));
        ev[rank] = ((long long)g_argm_ev[t] << 32) | (unsigned)t;
    }
    __syncthreads();

    // Phase B: warp-speculative batch loop (warp 0 only)
    if (t < 32) {
        const unsigned FULL = 0xFFFFFFFFu;
        int E = sE;
        int base = 0;
        while (base < E) {
            long long ee = ev[base + lane];
            int m   = (int)(ee >> 32);
            int lab = (int)(ee & 0xFFFFFFFFLL);
            atomicMin(&stamp[lab], lane);     // no dependence on r: issue early
            int r   = pinv[m];                // speculative (round-start state)
            int pl  = pinv[lab];
            int pr  = pinv[r];
            atomicMin(&stamp[r], lane);
            __syncwarp(FULL);
            int hz = (stamp[m] < lane) | (stamp[r] < lane) | (stamp[lab] < lane);
            unsigned bal = __ballot_sync(FULL, hz);
            int f = bal ? (__ffs(bal) - 1) : 32;    // f >= 1 always (lane 0 safe)
            stamp[r]   = 63;                   // reset stamps (post-ballot sync)
            stamp[lab] = 63;
            if (lane < f) {                    // commit conflict-free prefix
                pinv[r]   = pl;
                pinv[lab] = pr;
            }
            __syncwarp(FULL);
            base += f;
        }
    }
    __syncthreads();

    if (t < LBL) g_idx[t] = pinv[t];   // publish pinv
    __threadfence();
    __syncthreads();
    if (t == 0) atomicAdd(&g_done, 1u);        // release the gather
}

// ---------------------------------------------------------------------------
// K3: out[n, pinv[k]] = in[n, k]. Launched programmatically while k_scan runs:
// issues ALL row loads (MLP=8, wave-1 ~24 MB overlaps the scan), then spins on
// g_done. sidx read via __ldcg (L2-coherent). Scatter-STS + TMA bulk store.
// ---------------------------------------------------------------------------
__global__ __launch_bounds__(256) void k_gather(const float* __restrict__ in,
                                                float* __restrict__ out, int N) {
    __shared__ int4 sidx[250];                       // pinv, packed
    __shared__ __align__(16) float srow[8][1000];    // 4 KB slab per warp

    int t    = threadIdx.x;
    int wid  = t >> 5;
    int lane = t & 31;

    // ---- prework: all row loads in flight (overlaps k_scan) ---------------
    int row = blockIdx.x * 8 + wid;
    float4 v[8];
    if (row < N) {
        const float4* rp = reinterpret_cast<const float4*>(in + (size_t)row * 1000);
#pragma unroll
        for (int it = 0; it < 8; ++it) {
            int k = lane + it * 32;
            if (k < 250) v[it] = __ldcs(&rp[k]);
        }
    }

    // ---- wait for g_idx (monotonic flag; target snapshotted by k_fa) ------
    if (t == 0) {
        unsigned tgt = __ldcg(&g_target);
        while (__ldcg(&g_done) < tgt) __nanosleep(64);
    }
    __syncthreads();

    if (t < 250) sidx[t] = __ldcg(reinterpret_cast<const int4*>(g_idx) + t);
    __syncthreads();

    if (row < N) {
        float* my = &srow[wid][0];
#pragma unroll
        for (int it = 0; it < 8; ++it) {
            int k = lane + it * 32;
            if (k < 250) {
                int4 p = sidx[k];
                my[p.x] = v[it].x;     // permuted scatter into smem
                my[p.y] = v[it].y;
                my[p.z] = v[it].z;
                my[p.w] = v[it].w;
            }
        }
        // order the generic STS above before the async-proxy smem reads
        asm volatile("fence.proxy.async.shared::cta;" ::: "memory");
        __syncwarp();
        if (lane == 0) {
            uint32_t saddr = smem_u32(my);
            float*   gdst  = out + (size_t)row * 1000;
            asm volatile(
                "cp.async.bulk.global.shared::cta.bulk_group [%0], [%1], %2;"
                :: "l"(gdst), "r"(saddr), "r"(4000) : "memory");
            asm volatile("cp.async.bulk.commit_group;" ::: "memory");
            asm volatile("cp.async.bulk.wait_group 0;" ::: "memory");
        }
        __syncwarp();
    }
}

// ---------------------------------------------------------------------------
// host: PDL launches (programmatic stream serialization on the capture stream)
// ---------------------------------------------------------------------------
template <typename F, typename... Args>
static void launch_pdl(F func, dim3 grid, dim3 block, Args... args) {
    cudaLaunchConfig_t cfg = {};
    cfg.gridDim  = grid;
    cfg.blockDim = block;
    cfg.dynamicSmemBytes = 0;
    cfg.stream = 0;                      // legacy default stream (captured)
    cudaLaunchAttribute attr[1];
    attr[0].id = cudaLaunchAttributeProgrammaticStreamSerialization;
    attr[0].val.programmaticStreamSerializationAllowed = 1;
    cfg.attrs = attr;
    cfg.numAttrs = 1;
    cudaLaunchKernelEx(&cfg, func, args...);
}

extern "C" void kernel_launch(void* const* d_in, const int* in_sizes, int n_in,
                              void* d_out, int out_size) {
    const float* in     = (const float*)d_in[0];
    const int*   labels = (const int*)d_in[1];
    float*       out    = (float*)d_out;
    int N = in_sizes[1];   // 32768 rows; L = 1000

    k_fa<<<FAG, 256>>>(in, labels, N);
    launch_pdl(k_scan,   dim3(1),           dim3(1024), N);
    launch_pdl(k_gather, dim3((N + 7) / 8), dim3(256), in, out, N);
}